// round 5
// baseline (speedup 1.0000x reference)
#include <cuda_runtime.h>
#include <cstdint>
#include <math.h>

// Problem dims
#define B_   64
#define S_   512
#define I_   256
#define H_   512
#define G4H  2048          // 4*H
#define KTOT 768           // I + H
#define GRID 128           // CTAs (persistent, 1/SM); each owns 4 hidden indices
#define NTH  256

// ---------------- static device scratch (allocation-free rule) ----------------
__device__ __align__(16) float g_WU2[KTOT * G4H * 2];  // [k][col] duplicated pairs {w,w}
__device__ __align__(16) float g_xT [S_ * I_ * B_];     // [t][k][b]
__device__ __align__(16) float g_hT [H_ * B_];          // [hidden][b]
__device__ unsigned g_bar_cnt = 0;
__device__ volatile unsigned g_bar_sense = 0;

// SMEM layout: x slice [256][64] | h [512][64] | gates [16][64] | 2 mbarriers
#define SMEM_X_FLOATS (I_ * B_)          // 16384
#define SMEM_H_FLOATS (H_ * B_)          // 32768
#define SMEM_G_FLOATS (16 * B_)          // 1024
#define SMEM_BYTES ((SMEM_X_FLOATS + SMEM_H_FLOATS + SMEM_G_FLOATS) * 4 + 16)

// ---------------- PTX helpers ----------------
__device__ __forceinline__ unsigned sm2u(const void* p) {
    unsigned a;
    asm("{ .reg .u64 t; cvta.to.shared.u64 t, %1; cvt.u32.u64 %0, t; }"
        : "=r"(a) : "l"(p));
    return a;
}
__device__ __forceinline__ void mbar_init(unsigned a, unsigned c) {
    asm volatile("mbarrier.init.shared.b64 [%0], %1;" :: "r"(a), "r"(c) : "memory");
}
__device__ __forceinline__ void mbar_expect(unsigned a, unsigned bytes) {
    asm volatile("mbarrier.arrive.expect_tx.shared.b64 _, [%0], %1;"
                 :: "r"(a), "r"(bytes) : "memory");
}
__device__ __forceinline__ void bulk_g2s(unsigned dst, const void* src,
                                         unsigned bytes, unsigned mbar) {
    asm volatile(
        "cp.async.bulk.shared::cluster.global.mbarrier::complete_tx::bytes "
        "[%0], [%1], %2, [%3];"
        :: "r"(dst), "l"(src), "r"(bytes), "r"(mbar) : "memory");
}
__device__ __forceinline__ void mbar_wait(unsigned a, unsigned ph) {
    unsigned done = 0;
    while (!done) {
        asm volatile(
            "{ .reg .pred p; "
            "mbarrier.try_wait.parity.acquire.cta.shared::cta.b64 p, [%1], %2, 0x989680; "
            "selp.b32 %0, 1, 0, p; }"
            : "=r"(done) : "r"(a), "r"(ph) : "memory");
    }
}
__device__ __forceinline__ void fma2(unsigned long long& acc,
                                     unsigned long long a, unsigned long long b) {
    // packed fp32x2 FMA (Blackwell): 2 lane-FMAs per instruction
    asm("fma.rn.f32x2 %0, %1, %2, %0;" : "+l"(acc) : "l"(a), "l"(b));
}

// ---------------- prep kernel: build duplicated [W;U] weights, zero h ----------------
__global__ void k_prep(const float* __restrict__ W, const float* __restrict__ U) {
    int idx = blockIdx.x * blockDim.x + threadIdx.x;   // over KTOT*G4H = 1,572,864
    if (idx < KTOT * G4H) {
        int k = idx >> 11;        // /2048
        int c = idx & 2047;
        float w = (k < I_) ? W[k * G4H + c] : U[(k - I_) * G4H + c];
        reinterpret_cast<float2*>(g_WU2)[idx] = make_float2(w, w);
    }
    if (idx < H_ * B_) g_hT[idx] = 0.0f;
}

// ---------------- transpose x[b][t][k] -> g_xT[t][k][b] ----------------
__global__ void k_xT(const float* __restrict__ x) {
    __shared__ float ts[64][65];
    int t  = blockIdx.x;
    int k0 = blockIdx.y * 64;
    for (int i = threadIdx.x; i < 64 * 64; i += NTH) {
        int b = i >> 6, kk = i & 63;
        ts[b][kk] = x[(b * S_ + t) * I_ + k0 + kk];
    }
    __syncthreads();
    for (int i = threadIdx.x; i < 64 * 64; i += NTH) {
        int kk = i >> 6, b = i & 63;
        g_xT[(t * I_ + k0 + kk) * B_ + b] = ts[b][kk];
    }
}

// ---------------- persistent LSTM kernel ----------------
__global__ void __launch_bounds__(NTH, 1)
k_lstm(const float* __restrict__ bias, float* __restrict__ out) {
    extern __shared__ char smem[];
    float* smx = reinterpret_cast<float*>(smem);        // [256][64]
    float* smh = smx + SMEM_X_FLOATS;                   // [512][64]
    float* sg  = smh + SMEM_H_FLOATS;                   // [16][64]
    unsigned long long* mb =
        reinterpret_cast<unsigned long long*>(sg + SMEM_G_FLOATS);
    const unsigned mbx = sm2u(mb);
    const unsigned mbh = sm2u(mb + 1);
    const unsigned smx_u = sm2u(smx);
    const unsigned smh_u = sm2u(smh);

    const int tid = threadIdx.x;
    // GEMM mapping: 16 batch-groups x 16 gate-columns
    const int bg = tid & 15;            // batch group: b = bg*4 .. bg*4+3
    const int cg = tid >> 4;            // gate column: g = cg>>2, jl = cg&3
    const int colg = ((cg >> 2) * H_) + blockIdx.x * 4 + (cg & 3);
    const unsigned long long* wp =
        reinterpret_cast<const unsigned long long*>(g_WU2) + colg;
    // Update mapping: thread -> (jl, b); owns c state in a register
    const int jl = tid >> 6;            // 0..3
    const int bu = tid & 63;            // 0..63
    const int hcol = blockIdx.x * 4 + jl;
    float c_state = 0.0f;

    const float bs = bias[colg];
    unsigned long long bias2;
    asm("mov.b64 %0, {%1, %1};" : "=l"(bias2) : "f"(bs));

    if (tid == 0) {
        mbar_init(mbx, 1);
        mbar_init(mbh, 1);
        asm volatile("fence.proxy.async.shared::cta;" ::: "memory");
    }
    __syncthreads();
    if (tid == 0) {  // prefetch x slice for t=0
        mbar_expect(mbx, SMEM_X_FLOATS * 4);
        bulk_g2s(smx_u, g_xT, SMEM_X_FLOATS * 4, mbx);
    }

    for (int t = 0; t < S_; ++t) {
        const unsigned ph = (unsigned)(t & 1);

        // kick off h broadcast copy (overlaps with x-part compute)
        if (tid == 0) {
            mbar_expect(mbh, SMEM_H_FLOATS * 4);
            bulk_g2s(smh_u, g_hT, SMEM_H_FLOATS * 4, mbh);
        }

        unsigned long long a0 = bias2, a1 = bias2;   // (b0,b1) and (b2,b3)
        const unsigned long long* w = wp;

        // ---- x-part: k over I_, weights = W rows ----
        mbar_wait(mbx, ph);
        {
            const float* sp = smx + bg * 4;
            #pragma unroll 4
            for (int k = 0; k < I_; ++k) {
                ulonglong2 hv = *reinterpret_cast<const ulonglong2*>(sp);
                unsigned long long u = *w;
                sp += B_; w += G4H;
                fma2(a0, hv.x, u);
                fma2(a1, hv.y, u);
            }
        }
        // ---- h-part: k over H_, weights = U rows ----
        mbar_wait(mbh, ph);
        {
            const float* sp = smh + bg * 4;
            #pragma unroll 4
            for (int k = 0; k < H_; ++k) {
                ulonglong2 hv = *reinterpret_cast<const ulonglong2*>(sp);
                unsigned long long u = *w;
                sp += B_; w += G4H;
                fma2(a0, hv.x, u);
                fma2(a1, hv.y, u);
            }
        }

        // gate values -> smem exchange
        float4 gv;
        asm("mov.b64 {%0, %1}, %2;" : "=f"(gv.x), "=f"(gv.y) : "l"(a0));
        asm("mov.b64 {%0, %1}, %2;" : "=f"(gv.z), "=f"(gv.w) : "l"(a1));
        *reinterpret_cast<float4*>(sg + cg * B_ + bg * 4) = gv;
        __syncthreads();

        // prefetch next x slice (overlaps with update + barrier)
        if (tid == 0 && t + 1 < S_) {
            mbar_expect(mbx, SMEM_X_FLOATS * 4);
            bulk_g2s(smx_u, g_xT + (size_t)(t + 1) * I_ * B_,
                     SMEM_X_FLOATS * 4, mbx);
        }

        // ---- cell update for (bu, hcol) ----
        {
            float gi = sg[(0 * 4 + jl) * B_ + bu];
            float gf = sg[(1 * 4 + jl) * B_ + bu];
            float gg = sg[(2 * 4 + jl) * B_ + bu];
            float go = sg[(3 * 4 + jl) * B_ + bu];
            float iv = 1.0f / (1.0f + expf(-gi));
            float fv = 1.0f / (1.0f + expf(-gf));
            float gv2 = tanhf(gg);
            float ov = 1.0f / (1.0f + expf(-go));
            c_state = fv * c_state + iv * gv2;
            float hv2 = ov * tanhf(c_state);

            g_hT[hcol * B_ + bu] = hv2;                          // state for next step
            out[((size_t)bu * S_ + t) * H_ + hcol] = hv2;        // hidden_seq[b][t][h]
            if (t == S_ - 1) {
                size_t base = (size_t)B_ * S_ * H_;
                out[base + (size_t)bu * H_ + hcol] = hv2;                 // h_f
                out[base + (size_t)B_ * H_ + (size_t)bu * H_ + hcol] = c_state; // c_f
            }
        }

        // ---- grid barrier (sense-reversing; 512 toggles -> sense returns to 0) ----
        __syncthreads();
        if (tid == 0) {
            __threadfence();
            unsigned want = (unsigned)((t & 1) ^ 1);
            if (atomicAdd(&g_bar_cnt, 1u) == GRID - 1) {
                atomicExch(&g_bar_cnt, 0u);
                __threadfence();
                g_bar_sense = want;
            } else {
                while (g_bar_sense != want) { }
            }
            __threadfence();
        }
        __syncthreads();
    }
}

// ---------------- launch ----------------
extern "C" void kernel_launch(void* const* d_in, const int* in_sizes, int n_in,
                              void* d_out, int out_size) {
    const float* x = nullptr;
    const float* W = nullptr;
    const float* U = nullptr;
    const float* bias = nullptr;
    for (int i = 0; i < n_in; ++i) {
        switch (in_sizes[i]) {
            case B_ * S_ * I_: x    = (const float*)d_in[i]; break;  // 8388608
            case I_ * G4H:     W    = (const float*)d_in[i]; break;  // 524288
            case H_ * G4H:     U    = (const float*)d_in[i]; break;  // 1048576
            case G4H:          bias = (const float*)d_in[i]; break;  // 2048
            default: break;
        }
    }
    // fallback to positional order (x, W, U, bias) if sizes unexpected
    if (!x && n_in > 0)    x    = (const float*)d_in[0];
    if (!W && n_in > 1)    W    = (const float*)d_in[1];
    if (!U && n_in > 2)    U    = (const float*)d_in[2];
    if (!bias && n_in > 3) bias = (const float*)d_in[3];

    cudaFuncSetAttribute(k_lstm, cudaFuncAttributeMaxDynamicSharedMemorySize,
                         SMEM_BYTES);

    k_prep<<<(KTOT * G4H) / NTH, NTH>>>(W, U);      // 6144 blocks
    k_xT<<<dim3(S_, I_ / 64), NTH>>>(x);            // (512, 4)
    k_lstm<<<GRID, NTH, SMEM_BYTES>>>(bias, (float*)d_out);
}